// round 17
// baseline (speedup 1.0000x reference)
#include <cuda_runtime.h>
#include <cuda_bf16.h>
#include <math.h>

#define N_TAGS 48
#define ROOT 46
#define END_TAG 47
#define BATCH 512
#define MAXT 256
#define WARPS 4         // one sequence per warp, grid 128, 1 warp/SMSP

typedef unsigned long long ull;

// dynamic smem:
//   EF : float[WARPS][MAXT][N_TAGS]  = exp(feats)   (192 KB)
//   se : float[WARPS][2][N_TAGS]                    (1.5 KB)
#define FEATS_ELEMS (WARPS * MAXT * N_TAGS)
#define SE_OFF      (FEATS_ELEMS * 4)
#define SMEM_BYTES  (SE_OFF + WARPS * 2 * N_TAGS * 4)

__device__ __forceinline__ ull fma2(ull a, ull b, ull c) {
    ull d;
    asm("fma.rn.f32x2 %0, %1, %2, %3;" : "=l"(d) : "l"(a), "l"(b), "l"(c));
    return d;
}
__device__ __forceinline__ ull add2(ull a, ull b) {
    ull d;
    asm("add.rn.f32x2 %0, %1, %2;" : "=l"(d) : "l"(a), "l"(b));
    return d;
}
__device__ __forceinline__ ull pack2(float lo, float hi) {
    ull d;
    asm("mov.b64 %0, {%1, %2};" : "=l"(d) : "f"(lo), "f"(hi));
    return d;
}
__device__ __forceinline__ float sum2(ull a) {
    float lo, hi;
    asm("mov.b64 {%0, %1}, %2;" : "=f"(lo), "=f"(hi) : "l"(a));
    return lo + hi;
}
__device__ __forceinline__ float frcp(float x) {
    float y;
    asm("rcp.approx.f32 %0, %1;" : "=f"(y) : "f"(x));
    return y;
}

__global__ __launch_bounds__(32 * WARPS)
void crf_nll_kernel(const float* __restrict__ feats,
                    const int* __restrict__ tags,
                    const int* __restrict__ lengths,
                    const float* __restrict__ lt,
                    float* __restrict__ out)
{
    extern __shared__ __align__(16) char smem_raw[];
    float* EFall = (float*)smem_raw;                                  // exp(feats)
    float (*se)[2][N_TAGS] = (float (*)[2][N_TAGS])(smem_raw + SE_OFF);

    const int w = threadIdx.x >> 5;
    const int j = threadIdx.x & 31;
    const int jb = 32 + (j & 15);           // shared b-column this lane helps with
    const int b = blockIdx.x * WARPS + w;
    const bool hasB = (j < 16);

    const int len = lengths[b];
    const long fbase = (long)b * MAXT * N_TAGS;
    const int tbase = b * MAXT;

    // ------------- stage exp(feats) for all 4 sequences into smem ----------
    {
        const float4* src4 = (const float4*)(feats + (long)blockIdx.x * FEATS_ELEMS);
        float4* dst4 = (float4*)EFall;
        #pragma unroll 4
        for (int i = threadIdx.x; i < FEATS_ELEMS / 4; i += 32 * WARPS) {
            float4 v = src4[i];
            v.x = __expf(v.x); v.y = __expf(v.y);
            v.z = __expf(v.z); v.w = __expf(v.w);
            dst4[i] = v;
        }
    }

    // ------------- gold score + Σf0 (fp32, global; overlaps staging) -------
    float gold, sumf0;
    {
        float g = 0.0f, s0 = 0.0f;
        for (int t = j; t < MAXT; t += 32) {
            if (t < len) {
                int tg = tags[tbase + t];
                g += feats[fbase + t * N_TAGS + tg];
                if (t >= 1) {
                    int tp = tags[tbase + t - 1];
                    g += lt[tp * N_TAGS + tg];
                    s0 += feats[fbase + t * N_TAGS];   // f0 ledger (fp32)
                }
            }
        }
        if (j == 0) {
            int t0 = tags[tbase];
            int tl = tags[tbase + len - 1];
            g += lt[ROOT * N_TAGS + t0] + lt[tl * N_TAGS + END_TAG];
        }
        #pragma unroll
        for (int off = 16; off; off >>= 1) {
            g  += __shfl_xor_sync(0xffffffffu, g, off);
            s0 += __shfl_xor_sync(0xffffffffu, s0, off);
        }
        gold = g;
        sumf0 = s0;
    }

    // ------------- packed transition columns -------------------------------
    // EPa[k] = (exp lt[2k][j], exp lt[2k+1][j])       — own column j (24)
    // EPs[k] = (exp lt[ib+2k][jb], exp lt[ib+2k+1][jb]) — half of column jb (12)
    ull EPa[24], EPs[12];
    #pragma unroll
    for (int k = 0; k < 24; k++)
        EPa[k] = pack2(__expf(lt[(2 * k) * N_TAGS + j]),
                       __expf(lt[(2 * k + 1) * N_TAGS + j]));
    const int ib = hasB ? 0 : 24;           // i-range base for shared column
    #pragma unroll
    for (int k = 0; k < 12; k++)
        EPs[k] = pack2(__expf(lt[(ib + 2 * k) * N_TAGS + jb]),
                       __expf(lt[(ib + 2 * k + 1) * N_TAGS + jb]));
    const int kb0 = ib / 2;                 // W-index base (0 or 12)

    const float lt_end_a = lt[j * N_TAGS + END_TAG];
    const float lt_end_b = lt[jb * N_TAGS + END_TAG];

    // ------------- init (fp32 global, exact) --------------------------------
    float S = lt[ROOT * N_TAGS + 0] + feats[fbase + 0];
    float r_a = __expf(lt[ROOT * N_TAGS + j] + feats[fbase + j] - S);
    float r_b = hasB ? __expf(lt[ROOT * N_TAGS + jb] + feats[fbase + jb] - S) : 0.0f;

    __syncthreads();   // EF staged

    const float* EF = EFall + w * MAXT * N_TAGS;

    // lookahead: exp(f(t=1)) straight from smem
    float efa = EF[N_TAGS + j];
    float efb = EF[N_TAGS + jb];

    se[w][0][j] = r_a;
    if (hasB) se[w][0][32 + j] = r_b;
    __syncwarp();

    // ------------- forward recurrence: lean issue ---------------------------
    float Lacc = 0.0f;
    int cur = 0;
    const float* EFt = EF + N_TAGS;         // row t (starts at t=1)
    for (int t = 1; t < len; ++t, EFt += N_TAGS) {
        float ea = efa, eb = efb;           // exp(f(t)), ready

        // lookahead t+1 (row t+1 always within the smem allocation;
        // value is consumed only when t+1 < len)
        efa = EFt[N_TAGS + j];
        efb = EFt[N_TAGS + jb];

        float e0 = EFt[0];                  // broadcast LDS, replaces shfl
        float* RS = se[w][cur];
        float r0prev = RS[0];
        float inv = frcp(r0prev * e0);
        float ka = ea * inv;
        float kb = eb * inv;

        Lacc += __logf(r0prev);             // off-path ledger

        // --- dot: 36 fma2 total ---
        const ulonglong2* se2 = (const ulonglong2*)RS;
        ull W[24];
        #pragma unroll
        for (int i = 0; i < 12; i++) {
            ulonglong2 v = se2[i];
            W[2 * i] = v.x;
            W[2 * i + 1] = v.y;
        }
        // own column j: 24 fma2
        ull a0 = 0, a1 = 0, a2 = 0, a3 = 0;
        #pragma unroll
        for (int k = 0; k < 24; k += 4) {
            a0 = fma2(W[k + 0], EPa[k + 0], a0);
            a1 = fma2(W[k + 1], EPa[k + 1], a1);
            a2 = fma2(W[k + 2], EPa[k + 2], a2);
            a3 = fma2(W[k + 3], EPa[k + 3], a3);
        }
        float sa = sum2(add2(add2(a0, a1), add2(a2, a3)));
        // shared column jb: 12 fma2 (half the i-range per lane)
        ull c0 = 0, c1 = 0;
        #pragma unroll
        for (int k = 0; k < 12; k += 2) {
            c0 = fma2(W[kb0 + k], EPs[k], c0);
            c1 = fma2(W[kb0 + k + 1], EPs[k + 1], c1);
        }
        float ps = sum2(add2(c0, c1));
        float po = __shfl_xor_sync(0xffffffffu, ps, 16);
        float sb = ps + po;

        r_a = sa * ka;
        r_b = sb * kb;                      // meaningful in lanes 0-15

        float* RD = se[w][cur ^ 1];
        RD[j] = r_a;
        if (hasB) RD[32 + j] = r_b;
        __syncwarp();
        cur ^= 1;
    }

    // S_total = S0 + Σ log(r0prev) + Σ f0   (consistent with normalizer)
    S += Lacc + sumf0;

    // ------------- partition = lse over 48 terminal scores ------------------
    float pa = S + __logf(r_a) + lt_end_a;
    float pb = hasB ? (S + __logf(r_b) + lt_end_b) : -INFINITY;
    float m = fmaxf(pa, pb);
    #pragma unroll
    for (int off = 16; off; off >>= 1)
        m = fmaxf(m, __shfl_xor_sync(0xffffffffu, m, off));

    float ex = __expf(pa - m) + (hasB ? __expf(pb - m) : 0.0f);
    #pragma unroll
    for (int off = 16; off; off >>= 1)
        ex += __shfl_xor_sync(0xffffffffu, ex, off);

    if (j == 0)
        out[b] = m + __logf(ex) - gold;
}

extern "C" void kernel_launch(void* const* d_in, const int* in_sizes, int n_in,
                              void* d_out, int out_size)
{
    const float* feats = nullptr;
    const int*   tags = nullptr;
    const int*   lengths = nullptr;
    const float* lt = nullptr;

    for (int i = 0; i < n_in; i++) {
        switch (in_sizes[i]) {
            case BATCH * MAXT * N_TAGS: feats   = (const float*)d_in[i]; break;
            case BATCH * MAXT:          tags    = (const int*)d_in[i];   break;
            case BATCH:                 lengths = (const int*)d_in[i];   break;
            case N_TAGS * N_TAGS:       lt      = (const float*)d_in[i]; break;
        }
    }

    static bool attr_set = false;   // attribute config, not a guard on work
    if (!attr_set) {
        cudaFuncSetAttribute(crf_nll_kernel,
                             cudaFuncAttributeMaxDynamicSharedMemorySize,
                             SMEM_BYTES);
        attr_set = true;
    }

    crf_nll_kernel<<<BATCH / WARPS, 32 * WARPS, SMEM_BYTES>>>(
        feats, tags, lengths, lt, (float*)d_out);
}